// round 1
// baseline (speedup 1.0000x reference)
#include <cuda_runtime.h>
#include <math.h>

#define NB   2048
#define NDIM 128
#define MLZ  10
#define KAPPA 0.276f
#define TRI  8256   // 128*129/2

// Per-batch scratch: [0..NB) = max|lam|^2, [NB..2NB) = min|lam|^2.
// Fully overwritten by spectrum_kernel each launch before finalize reads it.
__device__ float g_scr[2 * NB];

__device__ __forceinline__ float blockReduceSum(float v, float* red, int tid) {
    #pragma unroll
    for (int o = 16; o > 0; o >>= 1)
        v += __shfl_xor_sync(0xffffffffu, v, o);
    __syncthreads();                 // protect red[] from previous use
    if ((tid & 31) == 0) red[tid >> 5] = v;
    __syncthreads();
    return red[0] + red[1] + red[2] + red[3];
}

// Number of eigenvalues of the 10x10 symmetric tridiagonal (a, b) less than x,
// via the LDL / Sturm sequence recurrence.
__device__ __forceinline__ int sturm_count(const float* a, const float* b2, float x) {
    float q = a[0] - x;
    int c = (q < 0.0f);
    #pragma unroll
    for (int i = 1; i < MLZ; i++) {
        float d = q;
        if (fabsf(d) < 1e-25f) d = (d < 0.0f) ? -1e-25f : 1e-25f;
        q = (a[i] - x) - b2[i - 1] / d;
        c += (q < 0.0f);
    }
    return c;
}

__global__ __launch_bounds__(128)
void spectrum_kernel(const float* __restrict__ net_out,
                     const float* __restrict__ U1,
                     const float* __restrict__ vin) {
    __shared__ float Lp[TRI];          // packed lower-triangular L, row-wise
    __shared__ float vcur[NDIM];
    __shared__ float vprev[NDIM];
    __shared__ float yv[NDIM];
    __shared__ float tv[NDIM];
    __shared__ float U1s[NDIM];
    __shared__ float red[4];
    __shared__ float alph[MLZ];
    __shared__ float bet[MLZ];
    __shared__ float sc[4];

    const int tid = threadIdx.x;
    const int b   = blockIdx.x;

    // ---- Load L (packed tri = tril_indices order), U1, v ----
    {
        const float4* Lg4 = (const float4*)(net_out + (size_t)b * TRI);
        float4* Lp4 = (float4*)Lp;
        for (int i = tid; i < TRI / 4; i += 128) Lp4[i] = Lg4[i];
    }
    U1s[tid] = U1[(size_t)b * NDIM + tid];
    float v0 = vin[(size_t)b * NDIM + tid];

    // vn = v / ||v||   (blockReduceSum's internal syncs also publish U1s, Lp not yet needed)
    float nrm = sqrtf(blockReduceSum(v0 * v0, red, tid));
    vcur[tid]  = v0 / nrm;
    vprev[tid] = 0.0f;

    // ---- dd_opt stencil constants (loop-invariant) ----
    // flat index n = i*16 + j*2 + c on the (8,8,2) lattice
    const int ii = tid >> 4, jj = (tid >> 1) & 7, cc = tid & 1;
    const int xip = (((ii + 1) & 7) << 4) | (jj << 1) | cc;
    const int xim = (((ii - 1) & 7) << 4) | (jj << 1) | cc;
    const int xjp = (ii << 4) | (((jj + 1) & 7) << 1) | cc;
    const int xjm = (ii << 4) | (((jj - 1) & 7) << 1) | cc;
    __syncthreads();  // U1s fully visible
    const float c_u0  = U1s[((ii << 3) + jj) << 1];
    const float c_u1  = U1s[(((ii << 3) + jj) << 1) + 1];
    const float c_u0m = U1s[((((ii - 1) & 7) << 3) + jj) << 1];
    const float c_u1m = U1s[(((ii << 3) + ((jj - 1) & 7)) << 1) + 1];

    float beta = 0.0f;
    __syncthreads();  // vcur, Lp visible

    // ---- Lanczos: 10 steps of Av(x) = L (L^T (D x)) ----
    for (int step = 0; step < MLZ; step++) {
        // D x  (Wilson-like hop stencil)
        {
            float xc  = vcur[tid];
            float hop = c_u0  * vcur[xip] + c_u1  * vcur[xjp]
                      + c_u0m * vcur[xim] + c_u1m * vcur[xjm];
            yv[tid] = xc - KAPPA * hop;
        }
        __syncthreads();

        // t_j = sum_{i>=j} L[i,j] * y_i    (thread tid = column j)
        // packed index tri(i)+j; consecutive across j at fixed i -> conflict-free
        {
            const int wbase = tid & ~31;                   // warp-uniform start row
            int off = (wbase * (wbase + 1)) / 2 + tid;     // tri(wbase) + j
            float acc = 0.0f;
            #pragma unroll 4
            for (int i = wbase; i < NDIM; i++) {
                float yi = yv[i];
                if (i >= tid) acc += Lp[off] * yi;
                off += i + 1;
            }
            tv[tid] = acc;
        }
        __syncthreads();

        // w_i = sum_{j<=i} L[i,j] * t_j    (thread tid = row i)
        // tri(i) mod 32 is a permutation within each warp -> conflict-free
        float wacc = 0.0f;
        {
            const int wend = tid | 31;                     // warp-uniform end
            const int base = (tid * (tid + 1)) / 2;
            #pragma unroll 4
            for (int j = 0; j <= wend; j++) {
                float tj = tv[j];
                if (j <= tid) wacc += Lp[base + j] * tj;
            }
        }

        // alpha = w . v_cur ; w -= alpha v_cur + beta v_prev ; beta_new = ||w||
        float al = blockReduceSum(wacc * vcur[tid], red, tid);
        float wn = wacc - al * vcur[tid] - beta * vprev[tid];
        float bn = sqrtf(blockReduceSum(wn * wn, red, tid));
        if (tid == 0) { alph[step] = al; bet[step] = bn; }
        vprev[tid] = vcur[tid];
        vcur[tid]  = wn / (bn + 1e-30f);
        beta = bn;
        __syncthreads();
    }

    // ---- Eigenvalues of tridiag T: need only lambda_0, lambda_9,
    //      and the two straddling zero. 4 lanes, Sturm bisection. ----
    if (tid < 4) {
        float a[MLZ], b2[MLZ - 1];
        #pragma unroll
        for (int i = 0; i < MLZ; i++) a[i] = alph[i];
        #pragma unroll
        for (int i = 0; i < MLZ - 1; i++) { float bb = bet[i]; b2[i] = bb * bb; }

        // Gershgorin bounds
        float lo = 3.0e38f, hi = -3.0e38f;
        #pragma unroll
        for (int i = 0; i < MLZ; i++) {
            float r = 0.0f;
            if (i > 0)       r += fabsf(bet[i - 1]);
            if (i < MLZ - 1) r += fabsf(bet[i]);
            lo = fminf(lo, a[i] - r);
            hi = fmaxf(hi, a[i] + r);
        }

        int nneg = sturm_count(a, b2, 0.0f);
        int k;
        if      (tid == 0) k = 0;
        else if (tid == 1) k = MLZ - 1;
        else if (tid == 2) { k = nneg - 1; if (k < 0) k = 0; if (k > MLZ - 1) k = MLZ - 1; }
        else               { k = nneg;     if (k > MLZ - 1) k = MLZ - 1; }

        float l = lo, h = hi;
        #pragma unroll 1
        for (int it = 0; it < 44; it++) {
            float mid = 0.5f * (l + h);
            if (sturm_count(a, b2, mid) > k) h = mid; else l = mid;
        }
        sc[tid] = fabsf(0.5f * (l + h));
    }
    __syncthreads();
    if (tid == 0) {
        float mx = fmaxf(sc[0], sc[1]);   // max |lambda|
        float mn = fminf(sc[2], sc[3]);   // min |lambda|
        g_scr[b]      = mx * mx;
        g_scr[NB + b] = mn * mn;
    }
}

__global__ __launch_bounds__(256)
void finalize_kernel(float* __restrict__ out) {
    const int tid = threadIdx.x;
    float s1 = 0.0f, s2 = 0.0f;
    for (int i = tid; i < NB; i += 256) {
        s1 += g_scr[i];
        s2 += g_scr[NB + i];
    }
    #pragma unroll
    for (int o = 16; o > 0; o >>= 1) {
        s1 += __shfl_xor_sync(0xffffffffu, s1, o);
        s2 += __shfl_xor_sync(0xffffffffu, s2, o);
    }
    __shared__ float r1[8], r2[8];
    if ((tid & 31) == 0) { r1[tid >> 5] = s1; r2[tid >> 5] = s2; }
    __syncthreads();
    if (tid == 0) {
        float S1 = 0.0f, S2 = 0.0f;
        #pragma unroll
        for (int w = 0; w < 8; w++) { S1 += r1[w]; S2 += r2[w]; }
        out[0] = (S1 - S2) * (1.0f / (float)NB);
    }
}

extern "C" void kernel_launch(void* const* d_in, const int* in_sizes, int n_in,
                              void* d_out, int out_size) {
    const float* net_out = (const float*)d_in[0];
    const float* U1      = (const float*)d_in[1];
    const float* v       = (const float*)d_in[2];
    (void)in_sizes; (void)n_in; (void)out_size;

    spectrum_kernel<<<NB, 128>>>(net_out, U1, v);
    finalize_kernel<<<1, 256>>>((float*)d_out);
}